// round 16
// baseline (speedup 1.0000x reference)
#include <cuda_runtime.h>
#include <cuda_fp16.h>
#include <cstdint>

#define TT 2048
#define BB 8
#define FD 768
#define HH 3
#define DH 256
#define MROWS (TT*BB)      // 16384
#define NBH (BB*HH)        // 24

// ------------------------- device scratch (static) -------------------------
__device__ __align__(16) __half g_x16[MROWS*FD];
__device__ __align__(16) __half g_wq16[FD*FD];
__device__ __align__(16) __half g_wk16[FD*FD];
__device__ __align__(16) __half g_wv16[FD*FD];
__device__ __align__(16) __half g_wo16[FD*FD];
__device__ __align__(16) __half g_q16[NBH*TT*DH];                    // Q fp16 (scaled)
__device__ __align__(16) __half g_k16[NBH*TT*DH];
__device__ __align__(16) __half g_v16[NBH*TT*DH];
__device__ __align__(16) __half g_o16[MROWS*FD];

// ------------------------------ PTX helpers --------------------------------
__device__ __forceinline__ uint32_t smem_u32(const void* p) {
    uint32_t a;
    asm("{ .reg .u64 t; cvta.to.shared.u64 t, %1; cvt.u32.u64 %0, t; }" : "=r"(a) : "l"(p));
    return a;
}
#define CP16(dst, src) \
    asm volatile("cp.async.cg.shared.global [%0], [%1], 16;" :: "r"(dst), "l"(src) : "memory")
#define CP_COMMIT() asm volatile("cp.async.commit_group;" ::: "memory")
#define CP_WAIT1()  asm volatile("cp.async.wait_group 1;" ::: "memory")

#define LDSM4(r, addr) \
    asm volatile("ldmatrix.sync.aligned.m8n8.x4.shared.b16 {%0,%1,%2,%3}, [%4];" \
        : "=r"((r)[0]), "=r"((r)[1]), "=r"((r)[2]), "=r"((r)[3]) : "r"(addr))
#define LDSM4T(r, addr) \
    asm volatile("ldmatrix.sync.aligned.m8n8.x4.trans.shared.b16 {%0,%1,%2,%3}, [%4];" \
        : "=r"((r)[0]), "=r"((r)[1]), "=r"((r)[2]), "=r"((r)[3]) : "r"(addr))

#define MMA16816H(d, a, b0v, b1v) \
    asm volatile("mma.sync.aligned.m16n8k16.row.col.f32.f16.f16.f32 " \
        "{%0,%1,%2,%3}, {%4,%5,%6,%7}, {%8,%9}, {%0,%1,%2,%3};" \
        : "+f"((d)[0]), "+f"((d)[1]), "+f"((d)[2]), "+f"((d)[3]) \
        : "r"((a)[0]), "r"((a)[1]), "r"((a)[2]), "r"((a)[3]), "r"(b0v), "r"(b1v))

#define SWZ(o) ((uint32_t)(o) ^ ((((uint32_t)(o)) >> 3) & 0x70))

#define QSCALE 0.1803368801111204f    // 0.125 * log2(e)

// ------- fp16 1-term GEMM (all projections), 256 thr, 2 CTAs/SM -------------
#define BM 128
#define BN 128
#define BK 32
#define ROWB 80
#define MAT_A (128*ROWB)              // 10240
#define MAT_B (128*ROWB)              // 10240
#define NSTAGE 3
#define G1_STG  (MAT_A + MAT_B)       // 20480
#define G1_SMEM (NSTAGE*G1_STG)       // 61440

// mode = blockIdx.z + mode_base: 0=Q (scaled fp16 out), 1=K, 2=V, 3=O (fp32 out)
__global__ __launch_bounds__(256, 2) void gemm_1t(
    const __half* __restrict__ A, int mode_base,
    const float* __restrict__ bq, const float* __restrict__ bk,
    const float* __restrict__ bv, const float* __restrict__ bo,
    float* __restrict__ outF)
{
    constexpr int OFF_A = 0;
    constexpr int OFF_B = MAT_A;

    extern __shared__ char smem[];
    const uint32_t sb = smem_u32(smem);

    const int tid = threadIdx.x;
    const int wid = tid >> 5, lane = tid & 31;
    const int wm = wid >> 2, wn = wid & 3;           // 2m x 4n
    const int m0 = blockIdx.x * BM, n0 = blockIdx.y * BN;
    const int mode = blockIdx.z + mode_base;
    const int K = FD;

    const __half* Bw = mode == 0 ? g_wq16 : mode == 1 ? g_wk16 : mode == 2 ? g_wv16 : g_wo16;
    const float* bias = mode == 0 ? bq : mode == 1 ? bk : mode == 2 ? bv : bo;

    float acc[4][4][4] = {};

    // 512 16B-chunks per matrix (128 rows x 4 chunks); 2 per thread each
    const int r0c = tid >> 2,          c0c = tid & 3;
    const int r1c = (tid + 256) >> 2,  c1c = (tid + 256) & 3;

    auto load_stage = [&](int kb, int s) {
        const uint32_t st = sb + s * G1_STG;
        {
            size_t ga = (size_t)(m0 + r0c) * K + kb * BK + c0c * 8;
            size_t gb = (size_t)(n0 + r0c) * K + kb * BK + c0c * 8;
            uint32_t so = r0c * ROWB + c0c * 16;
            CP16(st + OFF_A + so, A + ga);
            CP16(st + OFF_B + so, Bw + gb);
        }
        {
            size_t ga = (size_t)(m0 + r1c) * K + kb * BK + c1c * 8;
            size_t gb = (size_t)(n0 + r1c) * K + kb * BK + c1c * 8;
            uint32_t so = r1c * ROWB + c1c * 16;
            CP16(st + OFF_A + so, A + ga);
            CP16(st + OFF_B + so, Bw + gb);
        }
    };

    const int NKB = K / BK;
    load_stage(0, 0); CP_COMMIT();
    load_stage(1, 1); CP_COMMIT();

    const int a_row = wm * 64 + (lane & 7) + ((lane >> 3) & 1) * 8;
    const int a_kb  = ((lane >> 4) & 1) * 16;
    const int b_row = wn * 32 + (lane & 7) + (lane >= 16 ? 8 : 0);
    const int b_kb  = ((lane >> 3) & 1) * 16;

    for (int kb = 0; kb < NKB; kb++) {
        CP_WAIT1();
        __syncthreads();
        if (kb + 2 < NKB) load_stage(kb + 2, (kb + 2) % NSTAGE);
        CP_COMMIT();

        const uint32_t st = sb + (kb % NSTAGE) * G1_STG;
        #pragma unroll
        for (int ks = 0; ks < 2; ks++) {
            uint32_t bhf[2][4];
            #pragma unroll
            for (int np = 0; np < 2; np++) {
                uint32_t bo2 = (b_row + np * 16) * ROWB + b_kb + ks * 32;
                LDSM4(bhf[np], st + OFF_B + bo2);
            }
            #pragma unroll
            for (int mf = 0; mf < 4; mf++) {
                uint32_t ah[4];
                uint32_t ao = (a_row + mf * 16) * ROWB + a_kb + ks * 32;
                LDSM4(ah, st + OFF_A + ao);
                #pragma unroll
                for (int np = 0; np < 2; np++) {
                    MMA16816H(acc[mf][np*2],   ah, bhf[np][0], bhf[np][1]);
                    MMA16816H(acc[mf][np*2+1], ah, bhf[np][2], bhf[np][3]);
                }
            }
        }
        __syncthreads();
    }

    const int mrow = m0 + wm * 64 + (lane >> 2);
    const int ncol = n0 + wn * 32 + (lane & 3) * 2;
    const float oscale = (mode == 0) ? QSCALE : 1.0f;
    __half* dst = mode == 0 ? g_q16 : mode == 1 ? g_k16 : g_v16;

    #pragma unroll
    for (int mf = 0; mf < 4; mf++) {
        #pragma unroll
        for (int hi = 0; hi < 2; hi++) {
            const int m = mrow + mf * 16 + hi * 8;
            #pragma unroll
            for (int nf = 0; nf < 4; nf++) {
                const int n = ncol + nf * 8;
                float v0 = (acc[mf][nf][hi * 2]     + __ldg(&bias[n]))     * oscale;
                float v1 = (acc[mf][nf][hi * 2 + 1] + __ldg(&bias[n + 1])) * oscale;
                if (mode <= 2) {           // Q/K/V: (BH,T,D) fp16
                    const int t = m >> 3, b = m & 7, h = n >> 8, d = n & 255;
                    size_t o = ((size_t)(b * HH + h) * TT + t) * DH + d;
                    __half2 p; p.x = __float2half(v0); p.y = __float2half(v1);
                    *(__half2*)(dst + o) = p;
                } else {                   // O: fp32 (T*B, F)
                    float2 f; f.x = v0; f.y = v1;
                    *(float2*)(outF + (size_t)m * FD + n) = f;
                }
            }
        }
    }
}

// --------------------------- fused flash attention --------------------------
// CTA: 32 q-rows of one bh; 16 kv-tiles of 128 t. 128 threads (4 warps, 1m x 4n),
// 2 CTAs/SM (cross-CTA softmax/MMA overlap).
#define Q_OFF 0           // 16KB: 4 mats [32r x 64d] at j*4096
#define B0_OFF 16384      // 32KB: [dh 0/1][128t x 64d]
#define B1_OFF 49152      // 32KB
#define P_OFF 81920       // 8KB: two 4KB t-half mats [32r x 64t]
#define RMAX_OFF 90112    // [4 wn][32 rows]
#define RSUM_OFF 90624
#define ATT_SMEM 91136
#define NKV (TT/128)      // 16

__global__ __launch_bounds__(128, 2) void attn_kernel()
{
    extern __shared__ char sm[];
    const uint32_t sb = smem_u32(sm);
    const int tid = threadIdx.x, lane = tid & 31, wn = tid >> 5;   // 4 warps = 4n
    const int bh = blockIdx.y, m0 = blockIdx.x * 32;

    auto load_kv = [&](const __half* __restrict__ src, int tile, int c, uint32_t bufoff) {
        #pragma unroll
        for (int dh = 0; dh < 2; dh++) {
            #pragma unroll
            for (int i = 0; i < 8; i++) {
                int ci = tid + i * 128;
                int r = ci >> 3, cc = ci & 7;
                size_t g = ((size_t)bh * TT + tile * 128 + r) * DH + c * 128 + dh * 64 + cc * 8;
                CP16(sb + bufoff + dh * 16384 + SWZ(r * 128 + cc * 16), src + g);
            }
        }
    };

    #pragma unroll
    for (int i = 0; i < 8; i++) {
        int ci = tid + i * 128;
        int mat = ci >> 8, w = ci & 255, r = w >> 3, c = w & 7;
        size_t g = ((size_t)bh * TT + m0 + r) * DH + mat * 64 + c * 8;
        CP16(sb + Q_OFF + mat * 4096 + SWZ(r * 128 + c * 16), g_q16 + g);
    }
    load_kv(g_k16, 0, 0, B0_OFF); CP_COMMIT();
    load_kv(g_k16, 0, 1, B1_OFF); CP_COMMIT();

    const int a_rl = (lane & 7) + ((lane >> 3) & 1) * 8;
    const int a_kb = ((lane >> 4) & 1) * 16;
    const int b_rl = (lane & 7) + (lane >= 16 ? 8 : 0);
    const int b_kb = ((lane >> 3) & 1) * 16;
    const int v_rl = (lane & 7) + ((lane >> 3) & 1) * 8;
    const int v_cb = ((lane >> 4) & 1) * 16;

    float oacc[16][4] = {};
    float sacc[8][4];
    float mrun[2][2], lrun[2][2];
    #pragma unroll
    for (int i = 0; i < 2; i++)
        #pragma unroll
        for (int j = 0; j < 2; j++) { mrun[i][j] = -1e30f; lrun[i][j] = 0.f; }

    const int rl = lane >> 2;
    float* rmax = (float*)(sm + RMAX_OFF);
    float* rsum = (float*)(sm + RSUM_OFF);

    for (int tile = 0; tile < NKV; tile++) {
        #pragma unroll
        for (int f = 0; f < 8; f++) { sacc[f][0]=0.f; sacc[f][1]=0.f; sacc[f][2]=0.f; sacc[f][3]=0.f; }

        // ---- QK ----
        #pragma unroll
        for (int c = 0; c < 2; c++) {
            CP_WAIT1(); __syncthreads();
            const uint32_t kb_buf = sb + (c ? B1_OFF : B0_OFF);
            #pragma unroll
            for (int ks = 0; ks < 8; ks++) {
                const uint32_t qm = sb + Q_OFF + (c * 2 + (ks >> 2)) * 4096;
                const uint32_t km = kb_buf + (ks >> 2) * 16384;
                uint32_t q2[2][4], kh[2][4];
                #pragma unroll
                for (int mf = 0; mf < 2; mf++) {
                    uint32_t ao = SWZ((mf * 16 + a_rl) * 128 + (ks & 3) * 32 + a_kb);
                    LDSM4(q2[mf], qm + ao);
                }
                #pragma unroll
                for (int g = 0; g < 2; g++) {
                    uint32_t bo = SWZ((wn * 32 + g * 16 + b_rl) * 128 + (ks & 3) * 32 + b_kb);
                    LDSM4(kh[g], km + bo);
                }
                #pragma unroll
                for (int mf = 0; mf < 2; mf++)
                    #pragma unroll
                    for (int g = 0; g < 2; g++) {
                        MMA16816H(sacc[mf*4+g*2],   q2[mf], kh[g][0], kh[g][1]);
                        MMA16816H(sacc[mf*4+g*2+1], q2[mf], kh[g][2], kh[g][3]);
                    }
            }
            __syncthreads();
            load_kv(g_v16, tile, c, c ? B1_OFF : B0_OFF);
            CP_COMMIT();
        }

        // ---- online softmax ----
        float mx[2][2];
        #pragma unroll
        for (int mf = 0; mf < 2; mf++) { mx[mf][0] = -1e30f; mx[mf][1] = -1e30f; }
        #pragma unroll
        for (int f = 0; f < 8; f++) {
            const int mf = f >> 2;
            mx[mf][0] = fmaxf(mx[mf][0], fmaxf(sacc[f][0], sacc[f][1]));
            mx[mf][1] = fmaxf(mx[mf][1], fmaxf(sacc[f][2], sacc[f][3]));
        }
        #pragma unroll
        for (int mf = 0; mf < 2; mf++)
            #pragma unroll
            for (int hf = 0; hf < 2; hf++) {
                mx[mf][hf] = fmaxf(mx[mf][hf], __shfl_xor_sync(0xffffffffu, mx[mf][hf], 1));
                mx[mf][hf] = fmaxf(mx[mf][hf], __shfl_xor_sync(0xffffffffu, mx[mf][hf], 2));
            }
        if ((lane & 3) == 0) {
            #pragma unroll
            for (int mf = 0; mf < 2; mf++)
                #pragma unroll
                for (int hf = 0; hf < 2; hf++)
                    rmax[wn * 32 + mf * 16 + hf * 8 + rl] = mx[mf][hf];
        }
        __syncthreads();

        float aa[2][2];
        #pragma unroll
        for (int mf = 0; mf < 2; mf++)
            #pragma unroll
            for (int hf = 0; hf < 2; hf++) {
                const int row = mf * 16 + hf * 8 + rl;
                float mn = mrun[mf][hf];
                #pragma unroll
                for (int w = 0; w < 4; w++) mn = fmaxf(mn, rmax[w * 32 + row]);
                aa[mf][hf] = exp2f(mrun[mf][hf] - mn);
                mrun[mf][hf] = mn;
            }

        float ss[2][2] = {};
        #pragma unroll
        for (int f = 0; f < 8; f++) {
            const int mf = f >> 2;
            sacc[f][0] = exp2f(sacc[f][0] - mrun[mf][0]);
            sacc[f][1] = exp2f(sacc[f][1] - mrun[mf][0]);
            sacc[f][2] = exp2f(sacc[f][2] - mrun[mf][1]);
            sacc[f][3] = exp2f(sacc[f][3] - mrun[mf][1]);
            ss[mf][0] += sacc[f][0] + sacc[f][1];
            ss[mf][1] += sacc[f][2] + sacc[f][3];
        }
        #pragma unroll
        for (int mf = 0; mf < 2; mf++)
            #pragma unroll
            for (int hf = 0; hf < 2; hf++) {
                ss[mf][hf] += __shfl_xor_sync(0xffffffffu, ss[mf][hf], 1);
                ss[mf][hf] += __shfl_xor_sync(0xffffffffu, ss[mf][hf], 2);
            }
        if ((lane & 3) == 0) {
            #pragma unroll
            for (int mf = 0; mf < 2; mf++)
                #pragma unroll
                for (int hf = 0; hf < 2; hf++)
                    rsum[wn * 32 + mf * 16 + hf * 8 + rl] = ss[mf][hf];
        }

        {
            bool need = (aa[0][0] < 1.f) || (aa[0][1] < 1.f) ||
                        (aa[1][0] < 1.f) || (aa[1][1] < 1.f);
            if (__any_sync(0xffffffffu, need)) {
                #pragma unroll
                for (int f = 0; f < 16; f++) {
                    const int mf = (f >> 2) & 1;
                    oacc[f][0] *= aa[mf][0]; oacc[f][1] *= aa[mf][0];
                    oacc[f][2] *= aa[mf][1]; oacc[f][3] *= aa[mf][1];
                }
            }
        }

        // P -> smem
        {
            const int th = wn >> 1, cbase = (wn & 1) * 32;
            #pragma unroll
            for (int f = 0; f < 8; f++) {
                const int mf = f >> 2, g = (f >> 1) & 1, f8 = f & 1;
                const int colm = cbase + g * 16 + f8 * 8 + (lane & 3) * 2;
                const uint32_t pmo = P_OFF + th * 4096;
                __half2 p0; p0.x = __float2half(sacc[f][0]); p0.y = __float2half(sacc[f][1]);
                __half2 p1; p1.x = __float2half(sacc[f][2]); p1.y = __float2half(sacc[f][3]);
                uint32_t off = SWZ((mf * 16 + rl) * 128 + colm * 2);
                *(__half2*)(sm + pmo + off) = p0;
                off = SWZ((mf * 16 + 8 + rl) * 128 + colm * 2);
                *(__half2*)(sm + pmo + off) = p1;
            }
        }
        __syncthreads();

        #pragma unroll
        for (int mf = 0; mf < 2; mf++)
            #pragma unroll
            for (int hf = 0; hf < 2; hf++) {
                const int row = mf * 16 + hf * 8 + rl;
                float s = 0.f;
                #pragma unroll
                for (int w = 0; w < 4; w++) s += rsum[w * 32 + row];
                lrun[mf][hf] = lrun[mf][hf] * aa[mf][hf] + s;
            }

        // ---- AV ----
        #pragma unroll
        for (int c = 0; c < 2; c++) {
            CP_WAIT1(); __syncthreads();
            const uint32_t v_buf = sb + (c ? B1_OFF : B0_OFF) + (wn >> 1) * 16384;
            const int vcb = (wn & 1) * 64;
            #pragma unroll
            for (int ks = 0; ks < 8; ks++) {
                const uint32_t pm = sb + P_OFF + (ks >> 2) * 4096;
                uint32_t ph2[2][4], vh[2][4];
                #pragma unroll
                for (int mf = 0; mf < 2; mf++) {
                    uint32_t ao = SWZ((mf * 16 + a_rl) * 128 + (ks & 3) * 32 + a_kb);
                    LDSM4(ph2[mf], pm + ao);
                }
                const uint32_t vrow = ks * 16 + v_rl;
                #pragma unroll
                for (int g = 0; g < 2; g++) {
                    uint32_t bo = SWZ(vrow * 128 + vcb + g * 32 + v_cb);
                    LDSM4T(vh[g], v_buf + bo);
                }
                #pragma unroll
                for (int mf = 0; mf < 2; mf++)
                    #pragma unroll
                    for (int g = 0; g < 2; g++) {
                        MMA16816H(oacc[c*8+mf*4+g*2],   ph2[mf], vh[g][0], vh[g][1]);
                        MMA16816H(oacc[c*8+mf*4+g*2+1], ph2[mf], vh[g][2], vh[g][3]);
                    }
            }
            __syncthreads();
            if (tile + 1 < NKV) load_kv(g_k16, tile + 1, c, c ? B1_OFF : B0_OFF);
            CP_COMMIT();
        }
    }

    // ---- epilogue ----
    const int bb = bh / HH, hh = bh % HH;
    #pragma unroll
    for (int f = 0; f < 16; f++) {
        const int c = f >> 3, mf = (f >> 2) & 1, g = (f >> 1) & 1, f8 = f & 1;
        const int d = c * 128 + wn * 32 + g * 16 + f8 * 8 + (lane & 3) * 2;
        #pragma unroll
        for (int hf = 0; hf < 2; hf++) {
            const int t = m0 + mf * 16 + hf * 8 + rl;
            const float inv = 1.f / lrun[mf][hf];
            float v0 = oacc[f][hf*2] * inv, v1 = oacc[f][hf*2+1] * inv;
            size_t o = ((size_t)t * BB + bb) * FD + hh * DH + d;
            __half2 p; p.x = __float2half(v0); p.y = __float2half(v1);
            *(__half2*)(g_o16 + o) = p;
        }
    }
}

// ------------------------------ helper kernels ------------------------------
__global__ __launch_bounds__(256) void split_x_kernel(
    const float* __restrict__ in, int n4)
{
    int i = blockIdx.x * 256 + threadIdx.x;
    if (i >= n4) return;
    float4 v = *(const float4*)(in + (size_t)i * 4);
    __half2 p; p.x = __float2half(v.x); p.y = __float2half(v.y);
    __half2 q; q.x = __float2half(v.z); q.y = __float2half(v.w);
    *(__half2*)(g_x16 + (size_t)i*4)     = p;
    *(__half2*)(g_x16 + (size_t)i*4 + 2) = q;
}

__global__ __launch_bounds__(256) void split_w_kernel(
    const float* __restrict__ w0, const float* __restrict__ w1,
    const float* __restrict__ w2, const float* __restrict__ w3)
{
    const int which = blockIdx.y;
    int i = blockIdx.x * 256 + threadIdx.x;
    if (i >= FD*FD/4) return;
    const float* in = which == 0 ? w0 : which == 1 ? w1 : which == 2 ? w2 : w3;
    __half* h = which == 0 ? g_wq16 : which == 1 ? g_wk16 : which == 2 ? g_wv16 : g_wo16;
    float4 v = *(const float4*)(in + (size_t)i * 4);
    __half2 p; p.x=__float2half(v.x); p.y=__float2half(v.y);
    __half2 q; q.x=__float2half(v.z); q.y=__float2half(v.w);
    *(__half2*)(h + (size_t)i*4)     = p;
    *(__half2*)(h + (size_t)i*4 + 2) = q;
}

// --------------------------------- launch ----------------------------------
extern "C" void kernel_launch(void* const* d_in, const int* in_sizes, int n_in,
                              void* d_out, int out_size)
{
    const float* x  = (const float*)d_in[0];
    const float* Wq = (const float*)d_in[1];
    const float* bq = (const float*)d_in[2];
    const float* Wk = (const float*)d_in[3];
    const float* bk = (const float*)d_in[4];
    const float* Wv = (const float*)d_in[5];
    const float* bv = (const float*)d_in[6];
    const float* Wo = (const float*)d_in[7];
    const float* bo = (const float*)d_in[8];
    float* out = (float*)d_out;

    cudaFuncSetAttribute(gemm_1t,     cudaFuncAttributeMaxDynamicSharedMemorySize, G1_SMEM);
    cudaFuncSetAttribute(attn_kernel, cudaFuncAttributeMaxDynamicSharedMemorySize, ATT_SMEM);

    __half *x16, *o16;
    cudaGetSymbolAddress((void**)&x16, g_x16);
    cudaGetSymbolAddress((void**)&o16, g_o16);

    // 0: x split (fp16 single)
    split_x_kernel<<<(MROWS*FD/4 + 255)/256, 256>>>(x, MROWS*FD/4);
    // 1: W splits (all single fp16)
    dim3 gW((FD*FD/4 + 255)/256, 4);
    split_w_kernel<<<gW, 256>>>(Wq, Wk, Wv, Wo);
    // 2: fused QKV projection (fp16 1-term), z = 0,1,2; 2 CTAs/SM
    dim3 gQKV(MROWS/BM, FD/BN, 3);
    gemm_1t<<<gQKV, 256, G1_SMEM>>>(x16, 0, bq, bk, bv, bo, nullptr);
    // 3: fused flash attention (32 q-rows/CTA, 2 CTAs/SM)
    dim3 gA(TT/32, NBH);
    attn_kernel<<<gA, 128, ATT_SMEM>>>();
    // 4: output projection (fp16 1-term, mode 3)
    dim3 gO(MROWS/BM, FD/BN, 1);
    gemm_1t<<<gO, 256, G1_SMEM>>>(o16, 3, bq, bk, bv, bo, out);
}